// round 1
// baseline (speedup 1.0000x reference)
#include <cuda_runtime.h>
#include <math.h>

// ---------------------------------------------------------------------------
// Problem constants: B=1, S=1024, ca=1024, cz=64, cs=512, H=16, c=64
// ---------------------------------------------------------------------------

// Scratch (static device globals; allocation-free kernel_launch)
__device__ float g_an [1048576];   // LN(a)            [1024,1024]
__device__ float g_sn [ 524288];   // LN(s)*sn_w       [1024,512]
__device__ float g_a1 [1048576];   // adaLN output     [1024,1024]
__device__ float g_q  [1048576];   // Q                [1024,1024] == [16][1024][64]
__device__ float g_kvg[3145728];   // KVG              [1024,3072] == [16][1024][192]
__device__ float g_bias[16777216]; // bias -> scores -> softmax W (in place) [16][1024][1024]
__device__ float g_go [1048576];   // (g*o) flat       [16][1024][64] == [1024,1024]
__device__ float g_a2 [1048576];   // tmpP, later a2   [1024,1024]

__device__ __forceinline__ float sigmoidf_(float x){ return 1.f/(1.f+__expf(-x)); }

__device__ __forceinline__ float warpRedSum(float v){
#pragma unroll
    for (int o=16;o>0;o>>=1) v += __shfl_xor_sync(0xffffffffu, v, o);
    return v;
}
__device__ __forceinline__ float warpRedMax(float v){
#pragma unroll
    for (int o=16;o>0;o>>=1) v = fmaxf(v, __shfl_xor_sync(0xffffffffu, v, o));
    return v;
}

// ---------------------------------------------------------------------------
// LayerNorm over last dim (N <= 1024, N % 4 == 0). One block per row.
// w==nullptr -> no affine; else y *= w (no bias, matches reference usage).
// ---------------------------------------------------------------------------
__global__ __launch_bounds__(256)
void ln_k(const float* __restrict__ X, float* __restrict__ Y,
          const float* __restrict__ w, int N)
{
    long long row = blockIdx.x;
    const float4* x4 = reinterpret_cast<const float4*>(X + row*N);
    float4*       y4 = reinterpret_cast<float4*>(Y + row*N);
    const int tid = threadIdx.x, lane = tid & 31, wid = tid >> 5;
    const int n4 = N >> 2;
    __shared__ float r1[8], r2[8];

    float4 v = make_float4(0.f,0.f,0.f,0.f);
    float s = 0.f, ss = 0.f;
    bool act = tid < n4;
    if (act){
        v = x4[tid];
        s  = v.x+v.y+v.z+v.w;
        ss = v.x*v.x+v.y*v.y+v.z*v.z+v.w*v.w;
    }
    s = warpRedSum(s); ss = warpRedSum(ss);
    if (lane==0){ r1[wid]=s; r2[wid]=ss; }
    __syncthreads();
    float S=0.f, SS=0.f;
#pragma unroll
    for (int i=0;i<8;i++){ S+=r1[i]; SS+=r2[i]; }
    float invN = 1.f/(float)N;
    float m = S*invN;
    float rstd = rsqrtf(fmaf(-m, m, SS*invN) + 1e-5f);
    if (act){
        float4 o;
        o.x=(v.x-m)*rstd; o.y=(v.y-m)*rstd; o.z=(v.z-m)*rstd; o.w=(v.w-m)*rstd;
        if (w){
            float4 ww = reinterpret_cast<const float4*>(w)[tid];
            o.x*=ww.x; o.y*=ww.y; o.z*=ww.z; o.w*=ww.w;
        }
        y4[tid] = o;
    }
}

// ---------------------------------------------------------------------------
// Row softmax over 1024 elements, in place. One block (256 thr) per row.
// ---------------------------------------------------------------------------
__global__ __launch_bounds__(256)
void softmax_k(float* __restrict__ X)
{
    long long row = blockIdx.x;
    float4* x4 = reinterpret_cast<float4*>(X + row*1024);
    const int tid = threadIdx.x, lane = tid & 31, wid = tid >> 5;
    __shared__ float rm[8], rs[8];

    float4 v = x4[tid];
    float mx = fmaxf(fmaxf(v.x,v.y), fmaxf(v.z,v.w));
    mx = warpRedMax(mx);
    if (lane==0) rm[wid]=mx;
    __syncthreads();
    float M = rm[0];
#pragma unroll
    for (int i=1;i<8;i++) M = fmaxf(M, rm[i]);

    v.x=__expf(v.x-M); v.y=__expf(v.y-M); v.z=__expf(v.z-M); v.w=__expf(v.w-M);
    float s = v.x+v.y+v.z+v.w;
    s = warpRedSum(s);
    if (lane==0) rs[wid]=s;
    __syncthreads();
    float S=0.f;
#pragma unroll
    for (int i=0;i<8;i++) S += rs[i];
    float inv = 1.f/S;
    v.x*=inv; v.y*=inv; v.z*=inv; v.w*=inv;
    x4[tid] = v;
}

// ---------------------------------------------------------------------------
// z pipeline: per pixel (i,j): LN over 64 channels, then 16 head-dots, fused:
//   dot_h = rstd*(S_h - m*A_h) + B_h,  S_h = sum_c x_c * (pnorm_w[c]*bias_w[h,c])
// Output raw layout [i][j][h] (flat == reshaped [16][1024][1024]).
// 256 pixels/block, 128 threads (2 head-groups x 64), 4 pixels x 8 heads/thread.
// ---------------------------------------------------------------------------
constexpr int ZP = 256;
constexpr int ZTHREADS = 128;
constexpr int ZROW = 67;               // pad: 67 mod 32 = 3, gcd(3,32)=1 -> conflict-free
constexpr int ZSMEM_BYTES = (ZP*ZROW + 1024 + 32) * 4;

__global__ __launch_bounds__(ZTHREADS)
void zbias_k(const float* __restrict__ z,  const float* __restrict__ pnw,
             const float* __restrict__ pnb, const float* __restrict__ bw,
             const float* __restrict__ bb,  float* __restrict__ outp)
{
    extern __shared__ float sm[];
    float* xs = sm;                  // ZP*ZROW
    float* w2 = sm + ZP*ZROW;        // 16*64
    float* Av = w2 + 1024;           // 16
    float* Bv = Av + 16;             // 16
    const int tid = threadIdx.x;

    // coalesced load of 256x64 tile
    const float4* zb = reinterpret_cast<const float4*>(z + (long long)blockIdx.x*ZP*64);
#pragma unroll
    for (int it=0; it<(ZP*64/4)/ZTHREADS; it++){
        int idx = it*ZTHREADS + tid;
        float4 v = zb[idx];
        int flat = idx*4, pix = flat>>6, c = flat&63;
        float* d = &xs[pix*ZROW + c];
        d[0]=v.x; d[1]=v.y; d[2]=v.z; d[3]=v.w;
    }
    for (int i=tid;i<1024;i+=ZTHREADS) w2[i] = pnw[i&63]*bw[i];
    __syncthreads();
    if (tid<16){
        float A=0.f, Bc=0.f;
#pragma unroll
        for (int c=0;c<64;c++){ A += w2[tid*64+c]; Bc += pnb[c]*bw[tid*64+c]; }
        Av[tid]=A; Bv[tid]=Bc + bb[tid];
    }
    __syncthreads();

    const int hg = tid>>6, tp = tid&63;
    const int rb0=tp*ZROW, rb1=(tp+64)*ZROW, rb2=(tp+128)*ZROW, rb3=(tp+192)*ZROW;
    const float* wh = &w2[hg*8*64];
    float s1[4]={0,0,0,0}, s2[4]={0,0,0,0};
    float acc[8][4];
#pragma unroll
    for (int h=0;h<8;h++){ acc[h][0]=0; acc[h][1]=0; acc[h][2]=0; acc[h][3]=0; }

#pragma unroll 4
    for (int c=0;c<64;c++){
        float x0=xs[rb0+c], x1=xs[rb1+c], x2=xs[rb2+c], x3=xs[rb3+c];
        s1[0]+=x0; s2[0]=fmaf(x0,x0,s2[0]);
        s1[1]+=x1; s2[1]=fmaf(x1,x1,s2[1]);
        s1[2]+=x2; s2[2]=fmaf(x2,x2,s2[2]);
        s1[3]+=x3; s2[3]=fmaf(x3,x3,s2[3]);
#pragma unroll
        for (int h=0;h<8;h++){
            float w = wh[h*64+c];
            acc[h][0]=fmaf(x0,w,acc[h][0]);
            acc[h][1]=fmaf(x1,w,acc[h][1]);
            acc[h][2]=fmaf(x2,w,acc[h][2]);
            acc[h][3]=fmaf(x3,w,acc[h][3]);
        }
    }
    long long pixBase = (long long)blockIdx.x*ZP;
#pragma unroll
    for (int i=0;i<4;i++){
        float m   = s1[i]*(1.f/64.f);
        float var = fmaf(-m, m, s2[i]*(1.f/64.f));
        float rstd = rsqrtf(var + 1e-5f);
        long long p = pixBase + tp + 64*i;
#pragma unroll
        for (int h=0;h<8;h++){
            int hh = hg*8+h;
            outp[p*16 + hh] = fmaf(rstd, acc[h][i] - m*Av[hh], Bv[hh]);
        }
    }
}

// ---------------------------------------------------------------------------
// Generic fp32 tiled GEMM: C[m,n] = sum_k A(m,k)*B(n,k), with batch (blockIdx.z)
// ACOL: A(m,k) at A[k*lda+m] else A[m*lda+k].  BCOL: B(n,k) at B[k*ldb+n] else B[n*ldb+k].
// All M,N,K are exact multiples of tiles (no bounds checks).
// ---------------------------------------------------------------------------
enum { EPI_NONE=0, EPI_BIASN, EPI_A1, EPI_KVG, EPI_SCORES, EPI_OGEMM, EPI_OUT };

template<int BM,int BN,int BK,int TM,int TN,bool ACOL,bool BCOL,int EPI>
__global__ __launch_bounds__(256)
void gemm_k(const float* __restrict__ A, const float* __restrict__ B, float* __restrict__ C,
            int K, int lda, int ldb, int ldc, int N,
            long long aS, long long bS, long long cS,
            const float* __restrict__ e1, const float* __restrict__ e2,
            long long e1S, int e1ld, float scale)
{
    static_assert((BM/TM)*(BN/TN)==256, "256 threads");
    __shared__ __align__(16) float As[BK][BM+4];
    __shared__ __align__(16) float Bs[BK][BN+4];
    const int z = blockIdx.z;
    const float* Ab = A + (long long)z*aS;
    const float* Bb = B + (long long)z*bS;
    float*       Cb = C + (long long)z*cS;
    const int m0 = blockIdx.y*BM, n0 = blockIdx.x*BN;
    const int tid = threadIdx.x;
    constexpr int NT = BN/TN;
    const int tx = tid % NT, ty = tid / NT;

    float acc[TM][TN];
#pragma unroll
    for (int i=0;i<TM;i++)
#pragma unroll
        for (int j=0;j<TN;j++) acc[i][j]=0.f;

    for (int k0=0;k0<K;k0+=BK){
        if (ACOL){
            constexpr int V=BM/4, TOT=BK*V;
#pragma unroll
            for (int it=0;it<TOT;it+=256){
                int idx=it+tid; int kk=idx/V, mq=idx%V;
                float4 v=*reinterpret_cast<const float4*>(Ab + (long long)(k0+kk)*lda + m0 + mq*4);
                *reinterpret_cast<float4*>(&As[kk][mq*4]) = v;
            }
        } else {
            constexpr int V=BK/4, TOT=BM*V;
#pragma unroll
            for (int it=0;it<TOT;it+=256){
                int idx=it+tid; int mm=idx/V, kq=idx%V;
                float4 v=*reinterpret_cast<const float4*>(Ab + (long long)(m0+mm)*lda + k0 + kq*4);
                As[kq*4+0][mm]=v.x; As[kq*4+1][mm]=v.y; As[kq*4+2][mm]=v.z; As[kq*4+3][mm]=v.w;
            }
        }
        if (BCOL){
            constexpr int V=BN/4, TOT=BK*V;
#pragma unroll
            for (int it=0;it<TOT;it+=256){
                int idx=it+tid; int kk=idx/V, nq=idx%V;
                float4 v=*reinterpret_cast<const float4*>(Bb + (long long)(k0+kk)*ldb + n0 + nq*4);
                *reinterpret_cast<float4*>(&Bs[kk][nq*4]) = v;
            }
        } else {
            constexpr int V=BK/4, TOT=BN*V;
#pragma unroll
            for (int it=0;it<TOT;it+=256){
                int idx=it+tid; int nn=idx/V, kq=idx%V;
                float4 v=*reinterpret_cast<const float4*>(Bb + (long long)(n0+nn)*ldb + k0 + kq*4);
                Bs[kq*4+0][nn]=v.x; Bs[kq*4+1][nn]=v.y; Bs[kq*4+2][nn]=v.z; Bs[kq*4+3][nn]=v.w;
            }
        }
        __syncthreads();
#pragma unroll
        for (int kk=0;kk<BK;kk++){
            float a[TM], b[TN];
#pragma unroll
            for (int i=0;i<TM;i+=4)
                *reinterpret_cast<float4*>(&a[i]) = *reinterpret_cast<const float4*>(&As[kk][ty*TM+i]);
#pragma unroll
            for (int j=0;j<TN;j+=4)
                *reinterpret_cast<float4*>(&b[j]) = *reinterpret_cast<const float4*>(&Bs[kk][tx*TN+j]);
#pragma unroll
            for (int i=0;i<TM;i++)
#pragma unroll
                for (int j=0;j<TN;j++) acc[i][j] = fmaf(a[i], b[j], acc[i][j]);
        }
        __syncthreads();
    }

#pragma unroll
    for (int i=0;i<TM;i++){
        int m = m0 + ty*TM + i;
#pragma unroll
        for (int j=0;j<TN;j++){
            int n = n0 + tx*TN + j;
            long long ci = (long long)m*ldc + n;
            float v = acc[i][j];
            if constexpr (EPI==EPI_BIASN){
                v += e1[n];
            } else if constexpr (EPI==EPI_A1){
                // a1 = sigmoid(P * a_n + acc)
                v = sigmoidf_(fmaf(e1[(long long)m*N+n], e2[(long long)m*N+n], v));
            } else if constexpr (EPI==EPI_KVG){
                if (n % 192 >= 128) v = sigmoidf_(v);      // g-gate columns
            } else if constexpr (EPI==EPI_SCORES){
                v = fmaf(v, scale, Cb[ci]);                // += bias (in place)
            } else if constexpr (EPI==EPI_OGEMM){
                v *= e1[(long long)z*e1S + (long long)m*e1ld + n];   // * sigmoid(g)
            } else if constexpr (EPI==EPI_OUT){
                v = sigmoidf_(v + e1[n]) * e2[(long long)m*N + n];
            }
            Cb[ci] = v;
        }
    }
}

// ---------------------------------------------------------------------------
// Host launcher
// ---------------------------------------------------------------------------
static float* symAddr(const void* s){ void* p=nullptr; cudaGetSymbolAddress(&p, s); return (float*)p; }

extern "C" void kernel_launch(void* const* d_in, const int* in_sizes, int n_in,
                              void* d_out, int out_size)
{
    const float* a       = (const float*)d_in[0];
    const float* z       = (const float*)d_in[1];
    const float* sIn     = (const float*)d_in[2];
    const float* sn_w    = (const float*)d_in[3];
    const float* pb_w    = (const float*)d_in[4];
    const float* pb_b    = (const float*)d_in[5];
    const float* pn_w    = (const float*)d_in[6];
    const float* pnorm_w = (const float*)d_in[7];
    const float* pnorm_b = (const float*)d_in[8];
    const float* q_w     = (const float*)d_in[9];
    const float* q_b     = (const float*)d_in[10];
    const float* kvg_w   = (const float*)d_in[11];
    const float* bias_w  = (const float*)d_in[12];
    const float* bias_b  = (const float*)d_in[13];
    const float* attn_w  = (const float*)d_in[14];
    const float* out_w   = (const float*)d_in[15];
    const float* out_b   = (const float*)d_in[16];
    float* out = (float*)d_out;

    float* an   = symAddr(g_an);
    float* snp  = symAddr(g_sn);
    float* a1p  = symAddr(g_a1);
    float* qp   = symAddr(g_q);
    float* kvgp = symAddr(g_kvg);
    float* biasp= symAddr(g_bias);
    float* gop  = symAddr(g_go);
    float* a2p  = symAddr(g_a2);

    // 1-2: layernorms
    ln_k<<<1024,256>>>(a,   an,  nullptr, 1024);
    ln_k<<<1024,256>>>(sIn, snp, sn_w,    512);

    // 3: P = s_n @ pb_w.T + pb_b  (into g_a2 as temp)
    gemm_k<128,128,16,8,8,false,false,EPI_BIASN><<<dim3(8,8,1),256>>>(
        snp, pb_w, a2p, 512, 512,512,1024, 1024, 0,0,0, pb_b, nullptr, 0,0, 0.f);
    // 4: a1 = sigmoid(P*a_n + s_n @ pn_w.T)
    gemm_k<128,128,16,8,8,false,false,EPI_A1><<<dim3(8,8,1),256>>>(
        snp, pn_w, a1p, 512, 512,512,1024, 1024, 0,0,0, a2p, an, 0,0, 0.f);
    // 5: Q = a1 @ q_w.T + q_b
    gemm_k<128,128,16,8,8,false,false,EPI_BIASN><<<dim3(8,8,1),256>>>(
        a1p, q_w, qp, 1024, 1024,1024,1024, 1024, 0,0,0, q_b, nullptr, 0,0, 0.f);
    // 6: KVG = a1 @ kvg_w.T, sigmoid on g columns
    gemm_k<128,128,16,8,8,false,false,EPI_KVG><<<dim3(24,8,1),256>>>(
        a1p, kvg_w, kvgp, 1024, 1024,1024,3072, 3072, 0,0,0, nullptr, nullptr, 0,0, 0.f);
    // 7: z pipeline -> bias raw [i][j][h]
    cudaFuncSetAttribute(zbias_k, cudaFuncAttributeMaxDynamicSharedMemorySize, ZSMEM_BYTES);
    zbias_k<<<4096,ZTHREADS,ZSMEM_BYTES>>>(z, pnorm_w, pnorm_b, bias_w, bias_b, biasp);
    // 8: scores M = K_h Q_h^T / 64 + bias (in place in g_bias), batched over 16 heads
    gemm_k<128,128,16,8,8,false,false,EPI_SCORES><<<dim3(8,8,16),256>>>(
        kvgp, qp, biasp, 64, 192,64,1024, 1024,
        196608LL, 65536LL, 1048576LL, nullptr, nullptr, 0,0, 1.f/64.f);
    // 9: row softmax (in place): W
    softmax_k<<<16384,256>>>(biasp);
    // 10: O = W^T V, epilogue * g, write flat [h][j][c]
    gemm_k<128,64,16,8,4,true,true,EPI_OGEMM><<<dim3(1,8,16),256>>>(
        biasp, kvgp+64, gop, 1024, 1024,192,64, 64,
        1048576LL, 196608LL, 65536LL, kvgp+128, nullptr, 196608LL, 192, 0.f);
    // 11: a2 = (g*o) @ attn_w.T
    gemm_k<128,128,16,8,8,false,false,EPI_NONE><<<dim3(8,8,1),256>>>(
        gop, attn_w, a2p, 1024, 1024,1024,1024, 1024, 0,0,0, nullptr, nullptr, 0,0, 0.f);
    // 12: out = sigmoid(s @ out_w.T + out_b) * a2
    gemm_k<128,128,16,8,8,false,false,EPI_OUT><<<dim3(8,8,1),256>>>(
        sIn, out_w, out, 512, 512,512,1024, 1024, 0,0,0, out_b, a2p, 0,0, 0.f);
}

// round 3
// speedup vs baseline: 1.5506x; 1.5506x over previous
#include <cuda_runtime.h>
#include <math.h>

// ---------------------------------------------------------------------------
// Problem constants: B=1, S=1024, ca=1024, cz=64, cs=512, H=16, c=64
// ---------------------------------------------------------------------------

__device__ float g_an [1048576];   // LN(a)            [1024,1024]
__device__ float g_sn [ 524288];   // LN(s)*sn_w       [1024,512]
__device__ float g_a1 [1048576];   // adaLN output     [1024,1024]
__device__ float g_q  [1048576];   // Q                [1024,1024]
__device__ float g_kvg[3145728];   // KVG              [1024,3072]
__device__ float g_bias[16777216]; // bias -> scores -> softmax W (in place)
__device__ float g_go [1048576];   // (g*o) flat
__device__ float g_a2 [1048576];   // tmpP, later a2

__device__ __forceinline__ float sigmoidf_(float x){ return 1.f/(1.f+__expf(-x)); }
__device__ __forceinline__ unsigned tf32r(float x){
    unsigned r; asm("cvt.rna.tf32.f32 %0, %1;" : "=r"(r) : "f"(x)); return r;
}

__device__ __forceinline__ float warpRedSum(float v){
#pragma unroll
    for (int o=16;o>0;o>>=1) v += __shfl_xor_sync(0xffffffffu, v, o);
    return v;
}
__device__ __forceinline__ float warpRedMax(float v){
#pragma unroll
    for (int o=16;o>0;o>>=1) v = fmaxf(v, __shfl_xor_sync(0xffffffffu, v, o));
    return v;
}

// ---------------------------------------------------------------------------
// LayerNorm over last dim. One block per row.
// ---------------------------------------------------------------------------
__global__ __launch_bounds__(256)
void ln_k(const float* __restrict__ X, float* __restrict__ Y,
          const float* __restrict__ w, int N)
{
    long long row = blockIdx.x;
    const float4* x4 = reinterpret_cast<const float4*>(X + row*N);
    float4*       y4 = reinterpret_cast<float4*>(Y + row*N);
    const int tid = threadIdx.x, lane = tid & 31, wid = tid >> 5;
    const int n4 = N >> 2;
    __shared__ float r1[8], r2[8];

    float4 v = make_float4(0.f,0.f,0.f,0.f);
    float s = 0.f, ss = 0.f;
    bool act = tid < n4;
    if (act){
        v = x4[tid];
        s  = v.x+v.y+v.z+v.w;
        ss = v.x*v.x+v.y*v.y+v.z*v.z+v.w*v.w;
    }
    s = warpRedSum(s); ss = warpRedSum(ss);
    if (lane==0){ r1[wid]=s; r2[wid]=ss; }
    __syncthreads();
    float S=0.f, SS=0.f;
#pragma unroll
    for (int i=0;i<8;i++){ S+=r1[i]; SS+=r2[i]; }
    float invN = 1.f/(float)N;
    float m = S*invN;
    float rstd = rsqrtf(fmaf(-m, m, SS*invN) + 1e-5f);
    if (act){
        float4 o;
        o.x=(v.x-m)*rstd; o.y=(v.y-m)*rstd; o.z=(v.z-m)*rstd; o.w=(v.w-m)*rstd;
        if (w){
            float4 ww = reinterpret_cast<const float4*>(w)[tid];
            o.x*=ww.x; o.y*=ww.y; o.z*=ww.z; o.w*=ww.w;
        }
        y4[tid] = o;
    }
}

// ---------------------------------------------------------------------------
// Row softmax over 1024 elements, in place. One block (256 thr) per row.
// ---------------------------------------------------------------------------
__global__ __launch_bounds__(256)
void softmax_k(float* __restrict__ X)
{
    long long row = blockIdx.x;
    float4* x4 = reinterpret_cast<float4*>(X + row*1024);
    const int tid = threadIdx.x, lane = tid & 31, wid = tid >> 5;
    __shared__ float rm[8], rs[8];

    float4 v = x4[tid];
    float mx = fmaxf(fmaxf(v.x,v.y), fmaxf(v.z,v.w));
    mx = warpRedMax(mx);
    if (lane==0) rm[wid]=mx;
    __syncthreads();
    float M = rm[0];
#pragma unroll
    for (int i=1;i<8;i++) M = fmaxf(M, rm[i]);

    v.x=__expf(v.x-M); v.y=__expf(v.y-M); v.z=__expf(v.z-M); v.w=__expf(v.w-M);
    float s = v.x+v.y+v.z+v.w;
    s = warpRedSum(s);
    if (lane==0) rs[wid]=s;
    __syncthreads();
    float S=0.f;
#pragma unroll
    for (int i=0;i<8;i++) S += rs[i];
    float inv = 1.f/S;
    v.x*=inv; v.y*=inv; v.z*=inv; v.w*=inv;
    x4[tid] = v;
}

// ---------------------------------------------------------------------------
// z pipeline: fused LN(z)*w2 head-dots -> bias raw [i][j][h]
// ---------------------------------------------------------------------------
constexpr int ZP = 256;
constexpr int ZTHREADS = 128;
constexpr int ZROW = 67;
constexpr int ZSMEM_BYTES = (ZP*ZROW + 1024 + 32) * 4;

__global__ __launch_bounds__(ZTHREADS)
void zbias_k(const float* __restrict__ z,  const float* __restrict__ pnw,
             const float* __restrict__ pnb, const float* __restrict__ bw,
             const float* __restrict__ bb,  float* __restrict__ outp)
{
    extern __shared__ float sm[];
    float* xs = sm;
    float* w2 = sm + ZP*ZROW;
    float* Av = w2 + 1024;
    float* Bv = Av + 16;
    const int tid = threadIdx.x;

    const float4* zb = reinterpret_cast<const float4*>(z + (long long)blockIdx.x*ZP*64);
#pragma unroll
    for (int it=0; it<(ZP*64/4)/ZTHREADS; it++){
        int idx = it*ZTHREADS + tid;
        float4 v = zb[idx];
        int flat = idx*4, pix = flat>>6, c = flat&63;
        float* d = &xs[pix*ZROW + c];
        d[0]=v.x; d[1]=v.y; d[2]=v.z; d[3]=v.w;
    }
    for (int i=tid;i<1024;i+=ZTHREADS) w2[i] = pnw[i&63]*bw[i];
    __syncthreads();
    if (tid<16){
        float A=0.f, Bc=0.f;
#pragma unroll
        for (int c=0;c<64;c++){ A += w2[tid*64+c]; Bc += pnb[c]*bw[tid*64+c]; }
        Av[tid]=A; Bv[tid]=Bc + bb[tid];
    }
    __syncthreads();

    const int hg = tid>>6, tp = tid&63;
    const int rb0=tp*ZROW, rb1=(tp+64)*ZROW, rb2=(tp+128)*ZROW, rb3=(tp+192)*ZROW;
    const float* wh = &w2[hg*8*64];
    float s1[4]={0,0,0,0}, s2[4]={0,0,0,0};
    float acc[8][4];
#pragma unroll
    for (int h=0;h<8;h++){ acc[h][0]=0; acc[h][1]=0; acc[h][2]=0; acc[h][3]=0; }

#pragma unroll 4
    for (int c=0;c<64;c++){
        float x0=xs[rb0+c], x1=xs[rb1+c], x2=xs[rb2+c], x3=xs[rb3+c];
        s1[0]+=x0; s2[0]=fmaf(x0,x0,s2[0]);
        s1[1]+=x1; s2[1]=fmaf(x1,x1,s2[1]);
        s1[2]+=x2; s2[2]=fmaf(x2,x2,s2[2]);
        s1[3]+=x3; s2[3]=fmaf(x3,x3,s2[3]);
#pragma unroll
        for (int h=0;h<8;h++){
            float w = wh[h*64+c];
            acc[h][0]=fmaf(x0,w,acc[h][0]);
            acc[h][1]=fmaf(x1,w,acc[h][1]);
            acc[h][2]=fmaf(x2,w,acc[h][2]);
            acc[h][3]=fmaf(x3,w,acc[h][3]);
        }
    }
    long long pixBase = (long long)blockIdx.x*ZP;
#pragma unroll
    for (int i=0;i<4;i++){
        float m   = s1[i]*(1.f/64.f);
        float var = fmaf(-m, m, s2[i]*(1.f/64.f));
        float rstd = rsqrtf(var + 1e-5f);
        long long p = pixBase + tp + 64*i;
#pragma unroll
        for (int h=0;h<8;h++){
            int hh = hg*8+h;
            outp[p*16 + hh] = fmaf(rstd, acc[h][i] - m*Av[hh], Bv[hh]);
        }
    }
}

// ---------------------------------------------------------------------------
// TF32 tensor-core GEMM: C[m,n] = sum_k A(m,k)*B(n,k)  (+ batch via blockIdx.z)
// SMEM in fragment-permuted layout -> conflict-free lds.128/lds.64 frag loads.
// ---------------------------------------------------------------------------
enum { EPI_NONE=0, EPI_BIASN, EPI_A1, EPI_KVG, EPI_SCORES, EPI_OGEMM, EPI_OUT };

template<int BM>
__device__ __forceinline__ void stA(float* As, int m, int k, float v){
    int chunk = (k>>3)*(BM>>4) + (m>>4);
    int idx = chunk*128 + ((((m&7)<<2) | (k&3))<<2) + ((m>>3)&1) + (((k>>2)&1)<<1);
    As[idx] = __uint_as_float(tf32r(v));
}
template<int BN>
__device__ __forceinline__ void stB(float* Bs, int n, int k, float v){
    int chunk = (k>>3)*(BN>>3) + (n>>3);
    int idx = chunk*64 + ((((n&7)<<2) | (k&3))<<1) + ((k>>2)&1);
    Bs[idx] = __uint_as_float(tf32r(v));
}

__device__ __forceinline__ void mma_tf32(float* c, const uint4& a, const uint2& b){
    asm volatile("mma.sync.aligned.m16n8k8.row.col.f32.tf32.tf32.f32 "
        "{%0,%1,%2,%3}, {%4,%5,%6,%7}, {%8,%9}, {%0,%1,%2,%3};"
        : "+f"(c[0]),"+f"(c[1]),"+f"(c[2]),"+f"(c[3])
        : "r"(a.x),"r"(a.y),"r"(a.z),"r"(a.w), "r"(b.x),"r"(b.y));
}

template<int BM,int BN,int BK,int WGM,int WGN,bool ACOL,bool BCOL,int EPI>
__global__ __launch_bounds__(WGM*WGN*32)
void gemm_tc(const float* __restrict__ A, const float* __restrict__ B, float* __restrict__ C,
             int K, int lda, int ldb, int ldc, int N,
             long long aS, long long bS, long long cS,
             const float* __restrict__ e1, const float* __restrict__ e2,
             long long e1S, int e1ld, float scale)
{
    constexpr int NT  = WGM*WGN*32;
    constexpr int WM  = BM/WGM, WN = BN/WGN;
    constexpr int MFR = WM/16,  NFR = WN/8;
    __shared__ __align__(16) float As[(BK/8)*(BM/16)*128];
    __shared__ __align__(16) float Bs[(BK/8)*(BN/8)*64];

    const int z = blockIdx.z;
    const float* Ab = A + (long long)z*aS;
    const float* Bb = B + (long long)z*bS;
    float*       Cb = C + (long long)z*cS;
    const int m0 = blockIdx.y*BM, n0 = blockIdx.x*BN;
    const int tid = threadIdx.x, lane = tid&31, w = tid>>5;
    const int wr = w / WGN, wc = w % WGN;

    float acc[MFR][NFR][4];
#pragma unroll
    for (int i=0;i<MFR;i++)
#pragma unroll
        for (int j=0;j<NFR;j++){
            acc[i][j][0]=0.f; acc[i][j][1]=0.f; acc[i][j][2]=0.f; acc[i][j][3]=0.f;
        }

    for (int k0=0;k0<K;k0+=BK){
        if (ACOL){
#pragma unroll
            for (int it=0; it<BK*(BM/4); it+=NT){
                int idx=it+tid, kk=idx/(BM/4), mq=idx%(BM/4);
                float4 v = *reinterpret_cast<const float4*>(Ab + (long long)(k0+kk)*lda + m0 + mq*4);
                stA<BM>(As, mq*4+0, kk, v.x);
                stA<BM>(As, mq*4+1, kk, v.y);
                stA<BM>(As, mq*4+2, kk, v.z);
                stA<BM>(As, mq*4+3, kk, v.w);
            }
        } else {
#pragma unroll
            for (int it=0; it<BM*(BK/4); it+=NT){
                int idx=it+tid, mm=idx/(BK/4), kq=idx%(BK/4);
                float4 v = *reinterpret_cast<const float4*>(Ab + (long long)(m0+mm)*lda + k0 + kq*4);
                stA<BM>(As, mm, kq*4+0, v.x);
                stA<BM>(As, mm, kq*4+1, v.y);
                stA<BM>(As, mm, kq*4+2, v.z);
                stA<BM>(As, mm, kq*4+3, v.w);
            }
        }
        if (BCOL){
#pragma unroll
            for (int it=0; it<BK*(BN/4); it+=NT){
                int idx=it+tid, kk=idx/(BN/4), nq=idx%(BN/4);
                float4 v = *reinterpret_cast<const float4*>(Bb + (long long)(k0+kk)*ldb + n0 + nq*4);
                stB<BN>(Bs, nq*4+0, kk, v.x);
                stB<BN>(Bs, nq*4+1, kk, v.y);
                stB<BN>(Bs, nq*4+2, kk, v.z);
                stB<BN>(Bs, nq*4+3, kk, v.w);
            }
        } else {
#pragma unroll
            for (int it=0; it<BN*(BK/4); it+=NT){
                int idx=it+tid, nn=idx/(BK/4), kq=idx%(BK/4);
                float4 v = *reinterpret_cast<const float4*>(Bb + (long long)(n0+nn)*ldb + k0 + kq*4);
                stB<BN>(Bs, nn, kq*4+0, v.x);
                stB<BN>(Bs, nn, kq*4+1, v.y);
                stB<BN>(Bs, nn, kq*4+2, v.z);
                stB<BN>(Bs, nn, kq*4+3, v.w);
            }
        }
        __syncthreads();
#pragma unroll
        for (int ks=0;ks<BK/8;ks++){
            uint4 af[MFR]; uint2 bf[NFR];
#pragma unroll
            for (int i=0;i<MFR;i++)
                af[i] = *reinterpret_cast<const uint4*>(&As[(ks*(BM/16) + wr*MFR + i)*128 + lane*4]);
#pragma unroll
            for (int j=0;j<NFR;j++)
                bf[j] = *reinterpret_cast<const uint2*>(&Bs[(ks*(BN/8) + wc*NFR + j)*64 + lane*2]);
#pragma unroll
            for (int i=0;i<MFR;i++)
#pragma unroll
                for (int j=0;j<NFR;j++)
                    mma_tf32(acc[i][j], af[i], bf[j]);
        }
        __syncthreads();
    }

    // epilogue
    const int g = lane>>2, t = lane&3;
#pragma unroll
    for (int i=0;i<MFR;i++){
#pragma unroll
        for (int j=0;j<NFR;j++){
            int n = n0 + wc*WN + j*8 + 2*t;
#pragma unroll
            for (int half=0; half<2; half++){
                int m = m0 + wr*WM + i*16 + g + 8*half;
                float v0 = acc[i][j][half*2+0];
                float v1 = acc[i][j][half*2+1];
                long long ci = (long long)m*ldc + n;
                if constexpr (EPI==EPI_BIASN){
                    v0 += e1[n]; v1 += e1[n+1];
                } else if constexpr (EPI==EPI_A1){
                    float2 p  = *reinterpret_cast<const float2*>(&e1[(long long)m*N+n]);
                    float2 av = *reinterpret_cast<const float2*>(&e2[(long long)m*N+n]);
                    v0 = sigmoidf_(fmaf(p.x, av.x, v0));
                    v1 = sigmoidf_(fmaf(p.y, av.y, v1));
                } else if constexpr (EPI==EPI_KVG){
                    if (n % 192 >= 128){ v0 = sigmoidf_(v0); v1 = sigmoidf_(v1); }
                } else if constexpr (EPI==EPI_SCORES){
                    float2 b = *reinterpret_cast<const float2*>(&Cb[ci]);
                    v0 = fmaf(v0, scale, b.x);
                    v1 = fmaf(v1, scale, b.y);
                } else if constexpr (EPI==EPI_OGEMM){
                    float2 ga = *reinterpret_cast<const float2*>(&e1[(long long)z*e1S + (long long)m*e1ld + n]);
                    v0 *= ga.x; v1 *= ga.y;
                } else if constexpr (EPI==EPI_OUT){
                    float2 a2v = *reinterpret_cast<const float2*>(&e2[(long long)m*N+n]);
                    v0 = sigmoidf_(v0 + e1[n])   * a2v.x;
                    v1 = sigmoidf_(v1 + e1[n+1]) * a2v.y;
                }
                *reinterpret_cast<float2*>(&Cb[ci]) = make_float2(v0, v1);
            }
        }
    }
}

// ---------------------------------------------------------------------------
// Host launcher
// ---------------------------------------------------------------------------
static float* symAddr(const void* s){ void* p=nullptr; cudaGetSymbolAddress(&p, s); return (float*)p; }

extern "C" void kernel_launch(void* const* d_in, const int* in_sizes, int n_in,
                              void* d_out, int out_size)
{
    const float* a       = (const float*)d_in[0];
    const float* z       = (const float*)d_in[1];
    const float* sIn     = (const float*)d_in[2];
    const float* sn_w    = (const float*)d_in[3];
    const float* pb_w    = (const float*)d_in[4];
    const float* pb_b    = (const float*)d_in[5];
    const float* pn_w    = (const float*)d_in[6];
    const float* pnorm_w = (const float*)d_in[7];
    const float* pnorm_b = (const float*)d_in[8];
    const float* q_w     = (const float*)d_in[9];
    const float* q_b     = (const float*)d_in[10];
    const float* kvg_w   = (const float*)d_in[11];
    const float* bias_w  = (const float*)d_in[12];
    const float* bias_b  = (const float*)d_in[13];
    const float* attn_w  = (const float*)d_in[14];
    const float* out_w   = (const float*)d_in[15];
    const float* out_b   = (const float*)d_in[16];
    float* out = (float*)d_out;

    float* an   = symAddr(g_an);
    float* snp  = symAddr(g_sn);
    float* a1p  = symAddr(g_a1);
    float* qp   = symAddr(g_q);
    float* kvgp = symAddr(g_kvg);
    float* biasp= symAddr(g_bias);
    float* gop  = symAddr(g_go);
    float* a2p  = symAddr(g_a2);

    // 1-2: layernorms
    ln_k<<<1024,256>>>(a,   an,  nullptr, 1024);
    ln_k<<<1024,256>>>(sIn, snp, sn_w,    512);

    // 3: P = s_n @ pb_w.T + pb_b (temp in g_a2)
    gemm_tc<128,128,32,2,4,false,false,EPI_BIASN><<<dim3(8,8,1),256>>>(
        snp, pb_w, a2p, 512, 512,512,1024, 1024, 0,0,0, pb_b, nullptr, 0,0, 0.f);
    // 4: a1 = sigmoid(P*a_n + s_n @ pn_w.T)
    gemm_tc<128,128,32,2,4,false,false,EPI_A1><<<dim3(8,8,1),256>>>(
        snp, pn_w, a1p, 512, 512,512,1024, 1024, 0,0,0, a2p, an, 0,0, 0.f);
    // 5: Q = a1 @ q_w.T + q_b
    gemm_tc<128,128,32,2,4,false,false,EPI_BIASN><<<dim3(8,8,1),256>>>(
        a1p, q_w, qp, 1024, 1024,1024,1024, 1024, 0,0,0, q_b, nullptr, 0,0, 0.f);
    // 6: KVG = a1 @ kvg_w.T, sigmoid on g columns
    gemm_tc<128,128,32,2,4,false,false,EPI_KVG><<<dim3(24,8,1),256>>>(
        a1p, kvg_w, kvgp, 1024, 1024,1024,3072, 3072, 0,0,0, nullptr, nullptr, 0,0, 0.f);
    // 7: z pipeline -> bias raw [i][j][h]
    cudaFuncSetAttribute(zbias_k, cudaFuncAttributeMaxDynamicSharedMemorySize, ZSMEM_BYTES);
    zbias_k<<<4096,ZTHREADS,ZSMEM_BYTES>>>(z, pnorm_w, pnorm_b, bias_w, bias_b, biasp);
    // 8: scores = K_h Q_h^T / 64 + bias (in place), batched over heads
    gemm_tc<128,128,32,2,4,false,false,EPI_SCORES><<<dim3(8,8,16),256>>>(
        kvgp, qp, biasp, 64, 192,64,1024, 1024,
        196608LL, 65536LL, 1048576LL, nullptr, nullptr, 0,0, 1.f/64.f);
    // 9: row softmax in place
    softmax_k<<<16384,256>>>(biasp);
    // 10: O = W^T V, epilogue * gate, flat [h][j][c]
    gemm_tc<128,64,32,4,2,true,true,EPI_OGEMM><<<dim3(1,8,16),256>>>(
        biasp, kvgp+64, gop, 1024, 1024,192,64, 64,
        1048576LL, 196608LL, 65536LL, kvgp+128, nullptr, 196608LL, 192, 0.f);
    // 11: a2 = (g*o) @ attn_w.T
    gemm_tc<128,128,32,2,4,false,false,EPI_NONE><<<dim3(8,8,1),256>>>(
        gop, attn_w, a2p, 1024, 1024,1024,1024, 1024, 0,0,0, nullptr, nullptr, 0,0, 0.f);
    // 12: out = sigmoid(s @ out_w.T + out_b) * a2
    gemm_tc<128,128,32,2,4,false,false,EPI_OUT><<<dim3(8,8,1),256>>>(
        sIn, out_w, out, 512, 512,512,1024, 1024, 0,0,0, out_b, a2p, 0,0, 0.f);
}

// round 5
// speedup vs baseline: 1.8442x; 1.1893x over previous
#include <cuda_runtime.h>
#include <math.h>

// ---------------------------------------------------------------------------
// Problem constants: B=1, S=1024, ca=1024, cz=64, cs=512, H=16, c=64
// ---------------------------------------------------------------------------

__device__ float g_an [1048576];   // LN(a)            [1024,1024]
__device__ float g_sn [ 524288];   // LN(s)*sn_w       [1024,512]
__device__ float g_a1 [1048576];   // adaLN output     [1024,1024]
__device__ float g_q  [1048576];   // Q                [1024,1024]
__device__ float g_kvg[3145728];   // KVG              [1024,3072]
__device__ float g_bias[16777216]; // bias -> scores -> softmax W (in place)
__device__ float g_go [1048576];   // (g*o) flat
__device__ float g_a2 [1048576];   // tmpP, later a2

__device__ __forceinline__ float sigmoidf_(float x){ return 1.f/(1.f+__expf(-x)); }
__device__ __forceinline__ unsigned tf32r(float x){
    unsigned r; asm("cvt.rna.tf32.f32 %0, %1;" : "=r"(r) : "f"(x)); return r;
}

__device__ __forceinline__ float warpRedSum(float v){
#pragma unroll
    for (int o=16;o>0;o>>=1) v += __shfl_xor_sync(0xffffffffu, v, o);
    return v;
}
__device__ __forceinline__ float warpRedMax(float v){
#pragma unroll
    for (int o=16;o>0;o>>=1) v = fmaxf(v, __shfl_xor_sync(0xffffffffu, v, o));
    return v;
}

// ---------------------------------------------------------------------------
// LayerNorm over last dim. One block per row.
// ---------------------------------------------------------------------------
__global__ __launch_bounds__(256)
void ln_k(const float* __restrict__ X, float* __restrict__ Y,
          const float* __restrict__ w, int N)
{
    long long row = blockIdx.x;
    const float4* x4 = reinterpret_cast<const float4*>(X + row*N);
    float4*       y4 = reinterpret_cast<float4*>(Y + row*N);
    const int tid = threadIdx.x, lane = tid & 31, wid = tid >> 5;
    const int n4 = N >> 2;
    __shared__ float r1[8], r2[8];

    float4 v = make_float4(0.f,0.f,0.f,0.f);
    float s = 0.f, ss = 0.f;
    bool act = tid < n4;
    if (act){
        v = x4[tid];
        s  = v.x+v.y+v.z+v.w;
        ss = v.x*v.x+v.y*v.y+v.z*v.z+v.w*v.w;
    }
    s = warpRedSum(s); ss = warpRedSum(ss);
    if (lane==0){ r1[wid]=s; r2[wid]=ss; }
    __syncthreads();
    float S=0.f, SS=0.f;
#pragma unroll
    for (int i=0;i<8;i++){ S+=r1[i]; SS+=r2[i]; }
    float invN = 1.f/(float)N;
    float m = S*invN;
    float rstd = rsqrtf(fmaf(-m, m, SS*invN) + 1e-5f);
    if (act){
        float4 o;
        o.x=(v.x-m)*rstd; o.y=(v.y-m)*rstd; o.z=(v.z-m)*rstd; o.w=(v.w-m)*rstd;
        if (w){
            float4 ww = reinterpret_cast<const float4*>(w)[tid];
            o.x*=ww.x; o.y*=ww.y; o.z*=ww.z; o.w*=ww.w;
        }
        y4[tid] = o;
    }
}

// ---------------------------------------------------------------------------
// Row softmax over 1024 elements, in place. One block (256 thr) per row.
// ---------------------------------------------------------------------------
__global__ __launch_bounds__(256)
void softmax_k(float* __restrict__ X)
{
    long long row = blockIdx.x;
    float4* x4 = reinterpret_cast<float4*>(X + row*1024);
    const int tid = threadIdx.x, lane = tid & 31, wid = tid >> 5;
    __shared__ float rm[8], rs[8];

    float4 v = x4[tid];
    float mx = fmaxf(fmaxf(v.x,v.y), fmaxf(v.z,v.w));
    mx = warpRedMax(mx);
    if (lane==0) rm[wid]=mx;
    __syncthreads();
    float M = rm[0];
#pragma unroll
    for (int i=1;i<8;i++) M = fmaxf(M, rm[i]);

    v.x=__expf(v.x-M); v.y=__expf(v.y-M); v.z=__expf(v.z-M); v.w=__expf(v.w-M);
    float s = v.x+v.y+v.z+v.w;
    s = warpRedSum(s);
    if (lane==0) rs[wid]=s;
    __syncthreads();
    float S=0.f;
#pragma unroll
    for (int i=0;i<8;i++) S += rs[i];
    float inv = 1.f/S;
    v.x*=inv; v.y*=inv; v.z*=inv; v.w*=inv;
    x4[tid] = v;
}

// ---------------------------------------------------------------------------
// z pipeline: fused LN(z)*w2 head-dots -> bias raw [i][j][h]
// ---------------------------------------------------------------------------
constexpr int ZP = 256;
constexpr int ZTHREADS = 128;
constexpr int ZROW = 67;
constexpr int ZSMEM_BYTES = (ZP*ZROW + 1024 + 32) * 4;

__global__ __launch_bounds__(ZTHREADS)
void zbias_k(const float* __restrict__ z,  const float* __restrict__ pnw,
             const float* __restrict__ pnb, const float* __restrict__ bw,
             const float* __restrict__ bb,  float* __restrict__ outp)
{
    extern __shared__ float sm[];
    float* xs = sm;
    float* w2 = sm + ZP*ZROW;
    float* Av = w2 + 1024;
    float* Bv = Av + 16;
    const int tid = threadIdx.x;

    const float4* zb = reinterpret_cast<const float4*>(z + (long long)blockIdx.x*ZP*64);
#pragma unroll
    for (int it=0; it<(ZP*64/4)/ZTHREADS; it++){
        int idx = it*ZTHREADS + tid;
        float4 v = zb[idx];
        int flat = idx*4, pix = flat>>6, c = flat&63;
        float* d = &xs[pix*ZROW + c];
        d[0]=v.x; d[1]=v.y; d[2]=v.z; d[3]=v.w;
    }
    for (int i=tid;i<1024;i+=ZTHREADS) w2[i] = pnw[i&63]*bw[i];
    __syncthreads();
    if (tid<16){
        float A=0.f, Bc=0.f;
#pragma unroll
        for (int c=0;c<64;c++){ A += w2[tid*64+c]; Bc += pnb[c]*bw[tid*64+c]; }
        Av[tid]=A; Bv[tid]=Bc + bb[tid];
    }
    __syncthreads();

    const int hg = tid>>6, tp = tid&63;
    const int rb0=tp*ZROW, rb1=(tp+64)*ZROW, rb2=(tp+128)*ZROW, rb3=(tp+192)*ZROW;
    const float* wh = &w2[hg*8*64];
    float s1[4]={0,0,0,0}, s2[4]={0,0,0,0};
    float acc[8][4];
#pragma unroll
    for (int h=0;h<8;h++){ acc[h][0]=0; acc[h][1]=0; acc[h][2]=0; acc[h][3]=0; }

#pragma unroll 4
    for (int c=0;c<64;c++){
        float x0=xs[rb0+c], x1=xs[rb1+c], x2=xs[rb2+c], x3=xs[rb3+c];
        s1[0]+=x0; s2[0]=fmaf(x0,x0,s2[0]);
        s1[1]+=x1; s2[1]=fmaf(x1,x1,s2[1]);
        s1[2]+=x2; s2[2]=fmaf(x2,x2,s2[2]);
        s1[3]+=x3; s2[3]=fmaf(x3,x3,s2[3]);
#pragma unroll
        for (int h=0;h<8;h++){
            float w = wh[h*64+c];
            acc[h][0]=fmaf(x0,w,acc[h][0]);
            acc[h][1]=fmaf(x1,w,acc[h][1]);
            acc[h][2]=fmaf(x2,w,acc[h][2]);
            acc[h][3]=fmaf(x3,w,acc[h][3]);
        }
    }
    long long pixBase = (long long)blockIdx.x*ZP;
#pragma unroll
    for (int i=0;i<4;i++){
        float m   = s1[i]*(1.f/64.f);
        float var = fmaf(-m, m, s2[i]*(1.f/64.f));
        float rstd = rsqrtf(var + 1e-5f);
        long long p = pixBase + tp + 64*i;
#pragma unroll
        for (int h=0;h<8;h++){
            int hh = hg*8+h;
            outp[p*16 + hh] = fmaf(rstd, acc[h][i] - m*Av[hh], Bv[hh]);
        }
    }
}

// ---------------------------------------------------------------------------
// TF32 tensor-core GEMM, double-buffered SMEM + register-staged prefetch.
// C[m,n] = sum_k A(m,k)*B(n,k)  (+ batch via blockIdx.z)
// ---------------------------------------------------------------------------
enum { EPI_NONE=0, EPI_BIASN, EPI_A1, EPI_KVG, EPI_SCORES, EPI_OGEMM, EPI_OUT };

template<int BM>
__device__ __forceinline__ void stA(float* As, int m, int k, float v){
    int chunk = (k>>3)*(BM>>4) + (m>>4);
    int idx = chunk*128 + ((((m&7)<<2) | (k&3))<<2) + ((m>>3)&1) + (((k>>2)&1)<<1);
    As[idx] = __uint_as_float(tf32r(v));
}
template<int BN>
__device__ __forceinline__ void stB(float* Bs, int n, int k, float v){
    int chunk = (k>>3)*(BN>>3) + (n>>3);
    int idx = chunk*64 + ((((n&7)<<2) | (k&3))<<1) + ((k>>2)&1);
    Bs[idx] = __uint_as_float(tf32r(v));
}

__device__ __forceinline__ void mma_tf32(float* c, const uint4& a, const uint2& b){
    asm volatile("mma.sync.aligned.m16n8k8.row.col.f32.tf32.tf32.f32 "
        "{%0,%1,%2,%3}, {%4,%5,%6,%7}, {%8,%9}, {%0,%1,%2,%3};"
        : "+f"(c[0]),"+f"(c[1]),"+f"(c[2]),"+f"(c[3])
        : "r"(a.x),"r"(a.y),"r"(a.z),"r"(a.w), "r"(b.x),"r"(b.y));
}

template<int BM,int BN,int BK,int WGM,int WGN,bool ACOL,bool BCOL,int EPI>
__global__ __launch_bounds__(WGM*WGN*32)
void gemm_tc(const float* __restrict__ A, const float* __restrict__ B, float* __restrict__ C,
             int K, int lda, int ldb, int ldc, int N,
             long long aS, long long bS, long long cS,
             const float* __restrict__ e1, const float* __restrict__ e2,
             long long e1S, int e1ld, float scale)
{
    constexpr int NT  = WGM*WGN*32;
    constexpr int WM  = BM/WGM, WN = BN/WGN;
    constexpr int MFR = WM/16,  NFR = WN/8;
    constexpr int ASZ = (BK/8)*(BM/16)*128;
    constexpr int BSZ = (BK/8)*(BN/8)*64;
    constexpr int ANr = (BK*BM/4)/NT;
    constexpr int BNr = (BK*BN/4)/NT;
    extern __shared__ __align__(16) float smdyn[];

    const int z = blockIdx.z;
    const float* Ab = A + (long long)z*aS;
    const float* Bb = B + (long long)z*bS;
    float*       Cb = C + (long long)z*cS;
    const int m0 = blockIdx.y*BM, n0 = blockIdx.x*BN;
    const int tid = threadIdx.x, lane = tid&31, w = tid>>5;
    const int wr = w / WGN, wc = w % WGN;

    float4 aR[ANr], bR[BNr];

    auto ldG = [&](int k0){
#pragma unroll
        for (int u=0;u<ANr;u++){
            int idx=u*NT+tid;
            long long off;
            if (ACOL){ int kk=idx/(BM/4), mq=idx%(BM/4); off=(long long)(k0+kk)*lda + m0 + mq*4; }
            else      { int mm=idx/(BK/4), kq=idx%(BK/4); off=(long long)(m0+mm)*lda + k0 + kq*4; }
            aR[u] = *reinterpret_cast<const float4*>(Ab+off);
        }
#pragma unroll
        for (int u=0;u<BNr;u++){
            int idx=u*NT+tid;
            long long off;
            if (BCOL){ int kk=idx/(BN/4), nq=idx%(BN/4); off=(long long)(k0+kk)*ldb + n0 + nq*4; }
            else      { int nn=idx/(BK/4), kq=idx%(BK/4); off=(long long)(n0+nn)*ldb + k0 + kq*4; }
            bR[u] = *reinterpret_cast<const float4*>(Bb+off);
        }
    };
    auto stS = [&](int buf){
        float* As = smdyn + buf*ASZ;
        float* Bs = smdyn + 2*ASZ + buf*BSZ;
#pragma unroll
        for (int u=0;u<ANr;u++){
            int idx=u*NT+tid;
            if (ACOL){ int kk=idx/(BM/4), mq=idx%(BM/4);
                stA<BM>(As,mq*4+0,kk,aR[u].x); stA<BM>(As,mq*4+1,kk,aR[u].y);
                stA<BM>(As,mq*4+2,kk,aR[u].z); stA<BM>(As,mq*4+3,kk,aR[u].w);
            } else { int mm=idx/(BK/4), kq=idx%(BK/4);
                stA<BM>(As,mm,kq*4+0,aR[u].x); stA<BM>(As,mm,kq*4+1,aR[u].y);
                stA<BM>(As,mm,kq*4+2,aR[u].z); stA<BM>(As,mm,kq*4+3,aR[u].w);
            }
        }
#pragma unroll
        for (int u=0;u<BNr;u++){
            int idx=u*NT+tid;
            if (BCOL){ int kk=idx/(BN/4), nq=idx%(BN/4);
                stB<BN>(Bs,nq*4+0,kk,bR[u].x); stB<BN>(Bs,nq*4+1,kk,bR[u].y);
                stB<BN>(Bs,nq*4+2,kk,bR[u].z); stB<BN>(Bs,nq*4+3,kk,bR[u].w);
            } else { int nn=idx/(BK/4), kq=idx%(BK/4);
                stB<BN>(Bs,nn,kq*4+0,bR[u].x); stB<BN>(Bs,nn,kq*4+1,bR[u].y);
                stB<BN>(Bs,nn,kq*4+2,bR[u].z); stB<BN>(Bs,nn,kq*4+3,bR[u].w);
            }
        }
    };

    float acc[MFR][NFR][4];
#pragma unroll
    for (int i=0;i<MFR;i++)
#pragma unroll
        for (int j=0;j<NFR;j++){
            acc[i][j][0]=0.f; acc[i][j][1]=0.f; acc[i][j][2]=0.f; acc[i][j][3]=0.f;
        }

    ldG(0);
    stS(0);
    __syncthreads();
    const int nIter = K/BK;
    for (int it=0; it<nIter; it++){
        const int cur = it & 1;
        if (it+1 < nIter) ldG((it+1)*BK);     // prefetch next tile into registers
        const float* As = smdyn + cur*ASZ;
        const float* Bs = smdyn + 2*ASZ + cur*BSZ;
#pragma unroll
        for (int ks=0;ks<BK/8;ks++){
            uint4 af[MFR]; uint2 bf[NFR];
#pragma unroll
            for (int i=0;i<MFR;i++)
                af[i] = *reinterpret_cast<const uint4*>(&As[(ks*(BM/16) + wr*MFR + i)*128 + lane*4]);
#pragma unroll
            for (int j=0;j<NFR;j++)
                bf[j] = *reinterpret_cast<const uint2*>(&Bs[(ks*(BN/8) + wc*NFR + j)*64 + lane*2]);
#pragma unroll
            for (int i=0;i<MFR;i++)
#pragma unroll
                for (int j=0;j<NFR;j++)
                    mma_tf32(acc[i][j], af[i], bf[j]);
        }
        if (it+1 < nIter){
            stS(cur^1);
            __syncthreads();
        }
    }

    // epilogue
    const int g = lane>>2, t = lane&3;
#pragma unroll
    for (int i=0;i<MFR;i++){
#pragma unroll
        for (int j=0;j<NFR;j++){
            int n = n0 + wc*WN + j*8 + 2*t;
#pragma unroll
            for (int half=0; half<2; half++){
                int m = m0 + wr*WM + i*16 + g + 8*half;
                float v0 = acc[i][j][half*2+0];
                float v1 = acc[i][j][half*2+1];
                long long ci = (long long)m*ldc + n;
                if constexpr (EPI==EPI_BIASN){
                    v0 += e1[n]; v1 += e1[n+1];
                } else if constexpr (EPI==EPI_A1){
                    float2 p  = *reinterpret_cast<const float2*>(&e1[(long long)m*N+n]);
                    float2 av = *reinterpret_cast<const float2*>(&e2[(long long)m*N+n]);
                    v0 = sigmoidf_(fmaf(p.x, av.x, v0));
                    v1 = sigmoidf_(fmaf(p.y, av.y, v1));
                } else if constexpr (EPI==EPI_KVG){
                    if (n % 192 >= 128){ v0 = sigmoidf_(v0); v1 = sigmoidf_(v1); }
                } else if constexpr (EPI==EPI_SCORES){
                    float2 b = *reinterpret_cast<const float2*>(&Cb[ci]);
                    v0 = fmaf(v0, scale, b.x);
                    v1 = fmaf(v1, scale, b.y);
                } else if constexpr (EPI==EPI_OGEMM){
                    float2 ga = *reinterpret_cast<const float2*>(&e1[(long long)z*e1S + (long long)m*e1ld + n]);
                    v0 *= ga.x; v1 *= ga.y;
                } else if constexpr (EPI==EPI_OUT){
                    float2 a2v = *reinterpret_cast<const float2*>(&e2[(long long)m*N+n]);
                    v0 = sigmoidf_(v0 + e1[n])   * a2v.x;
                    v1 = sigmoidf_(v1 + e1[n+1]) * a2v.y;
                }
                *reinterpret_cast<float2*>(&Cb[ci]) = make_float2(v0, v1);
            }
        }
    }
}

// ---------------------------------------------------------------------------
// Host launcher
// ---------------------------------------------------------------------------
static float* symAddr(const void* s){ void* p=nullptr; cudaGetSymbolAddress(&p, s); return (float*)p; }

template<int BM,int BN,int WGM,int WGN,bool ACOL,bool BCOL,int EPI>
static void launch_gemm(dim3 grid,
                        const float* A, const float* B, float* C,
                        int K, int lda, int ldb, int ldc, int N,
                        long long aS, long long bS, long long cS,
                        const float* e1, const float* e2,
                        long long e1S, int e1ld, float scale)
{
    auto fn = gemm_tc<BM,BN,32,WGM,WGN,ACOL,BCOL,EPI>;
    constexpr int SMB = 2*((32/8)*(BM/16)*128 + (32/8)*(BN/8)*64)*4;
    cudaFuncSetAttribute(fn, cudaFuncAttributeMaxDynamicSharedMemorySize, SMB);
    fn<<<grid, WGM*WGN*32, SMB>>>(A,B,C,K,lda,ldb,ldc,N,aS,bS,cS,e1,e2,e1S,e1ld,scale);
}

extern "C" void kernel_launch(void* const* d_in, const int* in_sizes, int n_in,
                              void* d_out, int out_size)
{
    const float* a       = (const float*)d_in[0];
    const float* z       = (const float*)d_in[1];
    const float* sIn     = (const float*)d_in[2];
    const float* sn_w    = (const float*)d_in[3];
    const float* pb_w    = (const float*)d_in[4];
    const float* pb_b    = (const float*)d_in[5];
    const float* pn_w    = (const float*)d_in[6];
    const float* pnorm_w = (const float*)d_in[7];
    const float* pnorm_b = (const float*)d_in[8];
    const float* q_w     = (const float*)d_in[9];
    const float* q_b     = (const float*)d_in[10];
    const float* kvg_w   = (const float*)d_in[11];
    const float* bias_w  = (const float*)d_in[12];
    const float* bias_b  = (const float*)d_in[13];
    const float* attn_w  = (const float*)d_in[14];
    const float* out_w   = (const float*)d_in[15];
    const float* out_b   = (const float*)d_in[16];
    float* out = (float*)d_out;

    float* an   = symAddr(g_an);
    float* snp  = symAddr(g_sn);
    float* a1p  = symAddr(g_a1);
    float* qp   = symAddr(g_q);
    float* kvgp = symAddr(g_kvg);
    float* biasp= symAddr(g_bias);
    float* gop  = symAddr(g_go);
    float* a2p  = symAddr(g_a2);

    // 1-2: layernorms
    ln_k<<<1024,256>>>(a,   an,  nullptr, 1024);
    ln_k<<<1024,256>>>(sIn, snp, sn_w,    512);

    // 3: P = s_n @ pb_w.T + pb_b (temp in g_a2)
    launch_gemm<64,128,2,4,false,false,EPI_BIASN>(dim3(8,16,1),
        snp, pb_w, a2p, 512, 512,512,1024, 1024, 0,0,0, pb_b, nullptr, 0,0, 0.f);
    // 4: a1 = sigmoid(P*a_n + s_n @ pn_w.T)
    launch_gemm<64,128,2,4,false,false,EPI_A1>(dim3(8,16,1),
        snp, pn_w, a1p, 512, 512,512,1024, 1024, 0,0,0, a2p, an, 0,0, 0.f);
    // 5: Q = a1 @ q_w.T + q_b
    launch_gemm<64,128,2,4,false,false,EPI_BIASN>(dim3(8,16,1),
        a1p, q_w, qp, 1024, 1024,1024,1024, 1024, 0,0,0, q_b, nullptr, 0,0, 0.f);
    // 6: KVG = a1 @ kvg_w.T, sigmoid on g columns
    launch_gemm<64,128,2,4,false,false,EPI_KVG>(dim3(24,16,1),
        a1p, kvg_w, kvgp, 1024, 1024,1024,3072, 3072, 0,0,0, nullptr, nullptr, 0,0, 0.f);
    // 7: z pipeline -> bias raw [i][j][h]
    cudaFuncSetAttribute(zbias_k, cudaFuncAttributeMaxDynamicSharedMemorySize, ZSMEM_BYTES);
    zbias_k<<<4096,ZTHREADS,ZSMEM_BYTES>>>(z, pnorm_w, pnorm_b, bias_w, bias_b, biasp);
    // 8: scores = K_h Q_h^T / 64 + bias (in place), batched over heads
    launch_gemm<128,128,2,4,false,false,EPI_SCORES>(dim3(8,8,16),
        kvgp, qp, biasp, 64, 192,64,1024, 1024,
        196608LL, 65536LL, 1048576LL, nullptr, nullptr, 0,0, 1.f/64.f);
    // 9: row softmax in place
    softmax_k<<<16384,256>>>(biasp);
    // 10: O = W^T V, epilogue * gate, flat [h][j][c]
    launch_gemm<128,64,4,2,true,true,EPI_OGEMM>(dim3(1,8,16),
        biasp, kvgp+64, gop, 1024, 1024,192,64, 64,
        1048576LL, 196608LL, 65536LL, kvgp+128, nullptr, 196608LL, 192, 0.f);
    // 11: a2 = (g*o) @ attn_w.T
    launch_gemm<64,128,2,4,false,false,EPI_NONE>(dim3(8,16,1),
        gop, attn_w, a2p, 1024, 1024,1024,1024, 1024, 0,0,0, nullptr, nullptr, 0,0, 0.f);
    // 12: out = sigmoid(s @ out_w.T + out_b) * a2
    launch_gemm<64,128,2,4,false,false,EPI_OUT>(dim3(8,16,1),
        sIn, out_w, out, 512, 512,512,1024, 1024, 0,0,0, out_b, a2p, 0,0, 0.f);
}